// round 12
// baseline (speedup 1.0000x reference)
#include <cuda_runtime.h>

#define NDIM 1000
#define PDIM 50000
#define ZDIM 10
#define LDIM 5

#define NSPLIT 8
#define NCHUNK (NDIM / NSPLIT)                        // 125
#define K1_THREADS 256
#define K1_PTILE (K1_THREADS * 4)                     // 1024
#define K1_PTILES ((PDIM + K1_PTILE - 1) / K1_PTILE)  // 49
#define K1_MAIN (K1_PTILES * NSPLIT)                  // 392

#define K2_BLOCKS 49
#define K2_THREADS 512
#define K2_WARPS (K2_THREADS / 32)                    // 16
#define NSTEPS (ZDIM * LDIM)                          // 50

#define OUT_VW_OFF (LDIM * ZDIM * PDIM)               // 250000
#define OUT_AL_OFF (OUT_VW_OFF + LDIM * ZDIM)         // 250050

// Static device scratch (no runtime allocation allowed)
__device__ __align__(16) float g_ztrp[NSPLIT][ZDIM][PDIM];   // 16 MB partials
__device__ float g_mzz[ZDIM * ZDIM];
__device__ __align__(128) float2 g_part[NSTEPS][64];         // per-step (m, s) per block
__device__ int g_cnt[NSTEPS];                                // per-step arrival counters

// ---- R3/R8-proven rendezvous primitives (acquire-based detection ONLY:
// plain .cg polls of release-stored flags hang on this chip — R4/R5/R9) ----
__device__ __forceinline__ void publish(float2* slot, int* cnt, float m, float s) {
    asm volatile("st.global.v2.f32 [%0], {%1, %2};" :: "l"(slot), "f"(m), "f"(s) : "memory");
    // release-ordering: the v2 store is visible at gpu scope before the increment
    asm volatile("red.release.gpu.global.add.u32 [%0], 1;" :: "l"(cnt) : "memory");
}
__device__ __forceinline__ unsigned ld_acquire_u32(const int* p) {
    unsigned v;
    asm volatile("ld.acquire.gpu.global.u32 %0, [%1];" : "=r"(v) : "l"(p) : "memory");
    return v;
}

// one-exp online-softmax combine: (m,s) <- comb((m,s),(mo,so))
__device__ __forceinline__ void comb(float& m, float& s, float mo, float so) {
    float d = m - mo;
    float e = __expf(-fabsf(d));
    bool ge = (d >= 0.f);
    s = ge ? fmaf(so, e, s) : fmaf(s, e, so);
    m = ge ? m : mo;
}

// ---------------------------------------------------------------------------
// Kernel 1: ZtR partials — byte-identical to R8 (best measured: ~45us).
// ---------------------------------------------------------------------------
__global__ __launch_bounds__(K1_THREADS)
void k1_ztr(const float* __restrict__ data,
            const float* __restrict__ mean_z,
            const float* __restrict__ var_z,
            const float* __restrict__ tau_0,
            const float* __restrict__ tau_p,
            float* __restrict__ out_vw)
{
    const int b = blockIdx.x;
    const int tid = threadIdx.x;

    if (b == K1_MAIN) {
        if (tid < NSTEPS) g_cnt[tid] = 0;
        __shared__ float s_mzz[ZDIM * ZDIM];
        if (tid < ZDIM * ZDIM) {
            int i = tid / ZDIM, j = tid % ZDIM;
            float s = 0.f;
            for (int n = 0; n < NDIM; n++)
                s += mean_z[n * ZDIM + i] * mean_z[n * ZDIM + j];
            s += (float)NDIM * var_z[i * ZDIM + j];
            s_mzz[tid] = s;
            g_mzz[tid] = s;
        }
        __syncthreads();
        if (tid < LDIM * ZDIM) {
            int l = tid / ZDIM, k = tid % ZDIM;
            float tau = tau_p[0];
            out_vw[tid] = 1.0f / (tau * s_mzz[k * ZDIM + k] + tau_0[l * ZDIM + k]);
        }
        return;
    }

    const int pt = b % K1_PTILES;
    const int c  = b / K1_PTILES;

    __shared__ __align__(16) float s_z[NCHUNK][12];
    for (int i = tid; i < NCHUNK * ZDIM; i += K1_THREADS) {
        int n = i / ZDIM, kk = i % ZDIM;
        s_z[n][kk] = mean_z[(c * NCHUNK + n) * ZDIM + kk];
    }
    __syncthreads();

    const int p0 = pt * K1_PTILE + tid * 4;
    if (p0 >= PDIM) return;

    float4 acc[ZDIM];
#pragma unroll
    for (int k = 0; k < ZDIM; k++) acc[k] = make_float4(0.f, 0.f, 0.f, 0.f);

    const float* dptr = data + (size_t)c * NCHUNK * PDIM + p0;
#pragma unroll 2
    for (int n = 0; n < NCHUNK; n++) {
        float4 d = *reinterpret_cast<const float4*>(dptr + (size_t)n * PDIM);
        const float4* zr = reinterpret_cast<const float4*>(s_z[n]);
        float4 z0 = zr[0], z1 = zr[1], z2 = zr[2];
        float zk[ZDIM] = {z0.x, z0.y, z0.z, z0.w, z1.x, z1.y, z1.z, z1.w, z2.x, z2.y};
#pragma unroll
        for (int k = 0; k < ZDIM; k++) {
            acc[k].x = fmaf(zk[k], d.x, acc[k].x);
            acc[k].y = fmaf(zk[k], d.y, acc[k].y);
            acc[k].z = fmaf(zk[k], d.z, acc[k].z);
            acc[k].w = fmaf(zk[k], d.w, acc[k].w);
        }
    }
#pragma unroll
    for (int k = 0; k < ZDIM; k++)
        *reinterpret_cast<float4*>(&g_ztrp[c][k][p0]) = acc[k];
}

// ---------------------------------------------------------------------------
// Kernel 2: persistent sweep, 49 CTAs x 512. R8 detection (counter RED +
// acquire poll) but split-barrier tail: warps 1-15 bar.arrive and poll the
// counter themselves; every warp redundantly combines the 49 partials.
// Second __syncthreads + smem broadcast eliminated.
// ---------------------------------------------------------------------------
__global__ __launch_bounds__(K2_THREADS)
void k2_loop(const float* __restrict__ mw_in,
             const float* __restrict__ al_in,
             const float* __restrict__ pi,
             const float* __restrict__ tau_0,
             const float* __restrict__ tau_p,
             float* __restrict__ out)
{
    const int tid  = threadIdx.x;
    const int b    = blockIdx.x;
    const int wid  = tid >> 5;
    const int lane = tid & 31;

    float* out_mw = out;
    float* out_al = out + OUT_AL_OFF;

    __shared__ float s_mzz[ZDIM * ZDIM];
    __shared__ float2 s_c[NSTEPS];           // per-step (u_var, C2)
    __shared__ float2 s_red[K2_WARPS];

    if (tid < ZDIM * ZDIM) s_mzz[tid] = g_mzz[tid];
    const float tau = tau_p[0];

    const int p0 = b * (K2_THREADS * 2) + tid;     // max 49663 < PDIM
    const int p1 = p0 + K2_THREADS;
    const bool v1 = (p1 < PDIM);

    float W[ZDIM][2], Zt[ZDIM][2], lpi[ZDIM][2];
#pragma unroll
    for (int k = 0; k < ZDIM; k++) {
        {
            float zt = 0.f;
#pragma unroll
            for (int c = 0; c < NSPLIT; c++) zt += g_ztrp[c][k][p0];
            float w = 0.f;
#pragma unroll
            for (int l = 0; l < LDIM; l++) {
                size_t idx = (size_t)(l * ZDIM + k) * PDIM + p0;
                w = fmaf(mw_in[idx], al_in[idx], w);
            }
            Zt[k][0] = zt; W[k][0] = w;
            lpi[k][0] = __logf(pi[(size_t)k * PDIM + p0]);
        }
        if (v1) {
            float zt = 0.f;
#pragma unroll
            for (int c = 0; c < NSPLIT; c++) zt += g_ztrp[c][k][p1];
            float w = 0.f;
#pragma unroll
            for (int l = 0; l < LDIM; l++) {
                size_t idx = (size_t)(l * ZDIM + k) * PDIM + p1;
                w = fmaf(mw_in[idx], al_in[idx], w);
            }
            Zt[k][1] = zt; W[k][1] = w;
            lpi[k][1] = __logf(pi[(size_t)k * PDIM + p1]);
        } else { Zt[k][1] = 0.f; W[k][1] = 0.f; lpi[k][1] = 0.f; }
    }

    if (tid < NSTEPS) {
        int k = tid / LDIM, l = tid % LDIM;
        float Ezz  = g_mzz[k * ZDIM + k];
        float t0   = tau_0[l * ZDIM + k];
        float uv   = 1.f / (tau * Ezz + t0);
        float s2   = 1.f / (Ezz * tau);
        float s0i  = 1.f / t0;
        float C2   = 0.5f * (tau / Ezz) * (s0i / (s2 + s0i));
        s_c[k * LDIM + l] = make_float2(uv, C2);
    }
    __syncthreads();

#pragma unroll
    for (int k = 0; k < ZDIM; k++) {
        const float Ezz = s_mzz[k * ZDIM + k];
        float Rt[2], Wk[2];
#pragma unroll
        for (int e = 0; e < 2; e++) {
            float s = Zt[k][e];
#pragma unroll
            for (int j = 0; j < ZDIM; j++)
                s -= s_mzz[k * ZDIM + j] * W[j][e];
            Rt[e] = s + Ezz * W[k][e];
            Wk[e] = W[k][e];
        }

        float pw0, pw1;
        {
            size_t idx = (size_t)k * PDIM + p0;
            pw0 = mw_in[idx] * al_in[idx];
            pw1 = v1 ? mw_in[idx + K2_THREADS] * al_in[idx + K2_THREADS] : 0.f;
        }

        for (int l = 0; l < LDIM; l++) {
            const int step = k * LDIM + l;

            const int ln = (l + 1 < LDIM) ? l + 1 : l;
            const size_t nidx = (size_t)(ln * ZDIM + k) * PDIM + p0;
            float nm0 = mw_in[nidx], na0 = al_in[nidx];
            float nm1 = 0.f, na1 = 0.f;
            if (v1) { nm1 = mw_in[nidx + K2_THREADS]; na1 = al_in[nidx + K2_THREADS]; }

            const float2 uc    = s_c[step];
            const float u_var  = uc.x;
            const float C2     = uc.y;

            float Wkl0 = Wk[0] - pw0;
            float r0   = Rt[0] - Ezz * Wkl0;
            float lg0  = fmaf(C2 * r0, r0, lpi[k][0]);
            float Wkl1, r1, lg1;
            if (v1) {
                Wkl1 = Wk[1] - pw1;
                r1   = Rt[1] - Ezz * Wkl1;
                lg1  = fmaf(C2 * r1, r1, lpi[k][1]);
            } else { Wkl1 = 0.f; r1 = 0.f; lg1 = -1e30f; }

            // ---- warp-level online softmax reduce (m, s) ----
            float m = fmaxf(lg0, lg1);
            float s = __expf(lg0 - m) + __expf(lg1 - m);
#pragma unroll
            for (int o = 16; o > 0; o >>= 1) {
                float mo = __shfl_xor_sync(0xffffffffu, m, o);
                float so = __shfl_xor_sync(0xffffffffu, s, o);
                comb(m, s, mo, so);
            }
            // pre-detect: per-thread softmax numerators vs the warp max
            const float e0 = __expf(lg0 - m);
            const float e1 = v1 ? __expf(lg1 - m) : 0.f;

            if (lane == 0) s_red[wid] = make_float2(m, s);

            // ---- split barrier: producers arrive, warp 0 syncs+publishes ----
            if (wid == 0) {
                asm volatile("bar.sync 1, %0;" :: "r"(K2_THREADS) : "memory");
                // block-level reduce over 16 warp results
                float2 wv = (lane < K2_WARPS) ? s_red[lane] : make_float2(-1e30f, 0.f);
                float mb = wv.x, sb = wv.y;
#pragma unroll
                for (int o = 8; o > 0; o >>= 1) {
                    float mo = __shfl_xor_sync(0xffffffffu, mb, o);
                    float so = __shfl_xor_sync(0xffffffffu, sb, o);
                    comb(mb, sb, mo, so);
                }
                if (lane == 0)
                    publish(&g_part[step][b], &g_cnt[step], mb, sb);
            } else {
                asm volatile("bar.arrive 1, %0;" :: "r"(K2_THREADS) : "memory");
            }

            // ---- every warp: acquire-poll counter (one coalesced req/warp) ----
            while (ld_acquire_u32(&g_cnt[step]) < K2_BLOCKS) { }

            // ---- every warp: redundant grid combine (2 parallel .cg/lane) ----
            float2 v0 = __ldcg(&g_part[step][lane]);
            float2 v1g = (lane + 32 < K2_BLOCKS) ? __ldcg(&g_part[step][lane + 32])
                                                 : make_float2(-1e30f, 0.f);
            float ma = v0.x, sa = v0.y;
            comb(ma, sa, v1g.x, v1g.y);
#pragma unroll
            for (int o = 16; o > 0; o >>= 1) {
                float mo = __shfl_xor_sync(0xffffffffu, ma, o);
                float so = __shfl_xor_sync(0xffffffffu, sa, o);
                comb(ma, sa, mo, so);
            }
            const float gm = ma;   // identical in every lane of every warp
            const float gs = sa;

            // ---- normalize via precomputed numerators, update Wk, store ----
            const float corr = __expf(m - gm) * __frcp_rn(gs);
            {
                float a  = e0 * corr;
                float um = tau * u_var * r0;
                Wk[0] = Wkl0 + um * a;
                size_t idx = (size_t)(l * ZDIM + k) * PDIM + p0;
                out_mw[idx] = um;
                out_al[idx] = a;
            }
            if (v1) {
                float a  = e1 * corr;
                float um = tau * u_var * r1;
                Wk[1] = Wkl1 + um * a;
                size_t idx = (size_t)(l * ZDIM + k) * PDIM + p1;
                out_mw[idx] = um;
                out_al[idx] = a;
            }

            pw0 = nm0 * na0;
            pw1 = nm1 * na1;
        }
        W[k][0] = Wk[0];
        W[k][1] = Wk[1];
    }
}

// ---------------------------------------------------------------------------
extern "C" void kernel_launch(void* const* d_in, const int* in_sizes, int n_in,
                              void* d_out, int out_size)
{
    (void)in_sizes; (void)n_in; (void)out_size;
    const float* data   = (const float*)d_in[0];
    const float* mean_z = (const float*)d_in[1];
    const float* var_z  = (const float*)d_in[2];
    const float* mean_w = (const float*)d_in[3];
    // d_in[4] = var_w (unused: vw output fully overwritten)
    const float* alpha  = (const float*)d_in[5];
    const float* tau_0  = (const float*)d_in[6];
    const float* pi     = (const float*)d_in[7];
    const float* tau    = (const float*)d_in[8];
    float* out = (float*)d_out;

    k1_ztr<<<K1_MAIN + 1, K1_THREADS>>>(data, mean_z, var_z, tau_0, tau,
                                        out + OUT_VW_OFF);
    k2_loop<<<K2_BLOCKS, K2_THREADS>>>(mean_w, alpha, pi, tau_0, tau, out);
}

// round 13
// speedup vs baseline: 1.1516x; 1.1516x over previous
#include <cuda_runtime.h>

#define NDIM 1000
#define PDIM 50000
#define ZDIM 10
#define LDIM 5

#define NSPLIT 8
#define NCHUNK (NDIM / NSPLIT)                        // 125
#define K1_THREADS 256
#define K1_PTILE (K1_THREADS * 4)                     // 1024
#define K1_PTILES ((PDIM + K1_PTILE - 1) / K1_PTILE)  // 49
#define K1_MAIN (K1_PTILES * NSPLIT)                  // 392

#define K1B_BLOCKS (ZDIM * K1_PTILES)                 // 490

#define K2_BLOCKS 49
#define K2_THREADS 512
#define K2_WARPS (K2_THREADS / 32)                    // 16
#define NSTEPS (ZDIM * LDIM)                          // 50

#define OUT_VW_OFF (LDIM * ZDIM * PDIM)               // 250000
#define OUT_AL_OFF (OUT_VW_OFF + LDIM * ZDIM)         // 250050

// Static device scratch (no runtime allocation allowed)
__device__ __align__(16) float g_ztrp[NSPLIT][ZDIM][PDIM];   // 16 MB partials
__device__ __align__(16) float g_ztr[ZDIM][PDIM];            // reduced ZtR (2 MB)
__device__ __align__(16) float g_w0[ZDIM][PDIM];             // W0 = sum_l mw*al (2 MB)
__device__ float g_mzz[ZDIM * ZDIM];
__device__ __align__(128) float2 g_part[NSTEPS][64];         // per-step (m, s) per block
__device__ int g_cnt[NSTEPS];                                // per-step arrival counters

// ---- R3/R8-proven rendezvous primitives (acquire-based detection ONLY;
// ONE polling lane per CTA — all-warp polling regressed in R12, .cg flag
// polls hang per R4/R5/R9) ----
__device__ __forceinline__ void publish(float2* slot, int* cnt, float m, float s) {
    asm volatile("st.global.v2.f32 [%0], {%1, %2};" :: "l"(slot), "f"(m), "f"(s) : "memory");
    asm volatile("red.release.gpu.global.add.u32 [%0], 1;" :: "l"(cnt) : "memory");
}
__device__ __forceinline__ unsigned ld_acquire_u32(const int* p) {
    unsigned v;
    asm volatile("ld.acquire.gpu.global.u32 %0, [%1];" : "=r"(v) : "l"(p) : "memory");
    return v;
}

// one-exp online-softmax combine
__device__ __forceinline__ void comb(float& m, float& s, float mo, float so) {
    float d = m - mo;
    float e = __expf(-fabsf(d));
    bool ge = (d >= 0.f);
    s = ge ? fmaf(so, e, s) : fmaf(s, e, so);
    m = ge ? m : mo;
}

// ---------------------------------------------------------------------------
// Kernel 1: ZtR partials — byte-identical to R8 (best measured).
// ---------------------------------------------------------------------------
__global__ __launch_bounds__(K1_THREADS)
void k1_ztr(const float* __restrict__ data,
            const float* __restrict__ mean_z,
            const float* __restrict__ var_z,
            const float* __restrict__ tau_0,
            const float* __restrict__ tau_p,
            float* __restrict__ out_vw)
{
    const int b = blockIdx.x;
    const int tid = threadIdx.x;

    if (b == K1_MAIN) {
        if (tid < NSTEPS) g_cnt[tid] = 0;
        __shared__ float s_mzz[ZDIM * ZDIM];
        if (tid < ZDIM * ZDIM) {
            int i = tid / ZDIM, j = tid % ZDIM;
            float s = 0.f;
            for (int n = 0; n < NDIM; n++)
                s += mean_z[n * ZDIM + i] * mean_z[n * ZDIM + j];
            s += (float)NDIM * var_z[i * ZDIM + j];
            s_mzz[tid] = s;
            g_mzz[tid] = s;
        }
        __syncthreads();
        if (tid < LDIM * ZDIM) {
            int l = tid / ZDIM, k = tid % ZDIM;
            float tau = tau_p[0];
            out_vw[tid] = 1.0f / (tau * s_mzz[k * ZDIM + k] + tau_0[l * ZDIM + k]);
        }
        return;
    }

    const int pt = b % K1_PTILES;
    const int c  = b / K1_PTILES;

    __shared__ __align__(16) float s_z[NCHUNK][12];
    for (int i = tid; i < NCHUNK * ZDIM; i += K1_THREADS) {
        int n = i / ZDIM, kk = i % ZDIM;
        s_z[n][kk] = mean_z[(c * NCHUNK + n) * ZDIM + kk];
    }
    __syncthreads();

    const int p0 = pt * K1_PTILE + tid * 4;
    if (p0 >= PDIM) return;

    float4 acc[ZDIM];
#pragma unroll
    for (int k = 0; k < ZDIM; k++) acc[k] = make_float4(0.f, 0.f, 0.f, 0.f);

    const float* dptr = data + (size_t)c * NCHUNK * PDIM + p0;
#pragma unroll 2
    for (int n = 0; n < NCHUNK; n++) {
        float4 d = *reinterpret_cast<const float4*>(dptr + (size_t)n * PDIM);
        const float4* zr = reinterpret_cast<const float4*>(s_z[n]);
        float4 z0 = zr[0], z1 = zr[1], z2 = zr[2];
        float zk[ZDIM] = {z0.x, z0.y, z0.z, z0.w, z1.x, z1.y, z1.z, z1.w, z2.x, z2.y};
#pragma unroll
        for (int k = 0; k < ZDIM; k++) {
            acc[k].x = fmaf(zk[k], d.x, acc[k].x);
            acc[k].y = fmaf(zk[k], d.y, acc[k].y);
            acc[k].z = fmaf(zk[k], d.z, acc[k].z);
            acc[k].w = fmaf(zk[k], d.w, acc[k].w);
        }
    }
#pragma unroll
    for (int k = 0; k < ZDIM; k++)
        *reinterpret_cast<float4*>(&g_ztrp[c][k][p0]) = acc[k];
}

// ---------------------------------------------------------------------------
// Kernel 1b: full-chip reduction. Collapses the 8 ztrp partials into ZtR and
// computes W0[k][p] = sum_l mw*al — work k2's 49-SM grid did at 1/3 of chip
// bandwidth. Same summation order as R8's k2 init (bitwise identical).
// ---------------------------------------------------------------------------
__global__ __launch_bounds__(K1_THREADS)
void k1b_reduce(const float* __restrict__ mw_in,
                const float* __restrict__ al_in)
{
    const int b   = blockIdx.x;                 // 0..489
    const int k   = b / K1_PTILES;
    const int pt  = b % K1_PTILES;
    const int p0  = pt * K1_PTILE + threadIdx.x * 4;
    if (p0 >= PDIM) return;

    // ZtR: sum 8 partials (c ascending — matches R8's k2 init order)
    float4 zt = make_float4(0.f, 0.f, 0.f, 0.f);
#pragma unroll
    for (int c = 0; c < NSPLIT; c++) {
        float4 v = *reinterpret_cast<const float4*>(&g_ztrp[c][k][p0]);
        zt.x += v.x; zt.y += v.y; zt.z += v.z; zt.w += v.w;
    }
    *reinterpret_cast<float4*>(&g_ztr[k][p0]) = zt;

    // W0: fmaf over l ascending — matches R8's k2 init order
    float4 w = make_float4(0.f, 0.f, 0.f, 0.f);
#pragma unroll
    for (int l = 0; l < LDIM; l++) {
        size_t idx = (size_t)(l * ZDIM + k) * PDIM + p0;
        float4 mwv = *reinterpret_cast<const float4*>(mw_in + idx);
        float4 alv = *reinterpret_cast<const float4*>(al_in + idx);
        w.x = fmaf(mwv.x, alv.x, w.x);
        w.y = fmaf(mwv.y, alv.y, w.y);
        w.z = fmaf(mwv.z, alv.z, w.z);
        w.w = fmaf(mwv.w, alv.w, w.w);
    }
    *reinterpret_cast<float4*>(&g_w0[k][p0]) = w;
}

// ---------------------------------------------------------------------------
// Kernel 2: persistent sweep, 49 CTAs x 512, 2 cols/thread. Step loop is
// byte-identical to R8 (best measured); init reads pre-reduced ZtR/W0.
// ---------------------------------------------------------------------------
__global__ __launch_bounds__(K2_THREADS)
void k2_loop(const float* __restrict__ mw_in,
             const float* __restrict__ al_in,
             const float* __restrict__ pi,
             const float* __restrict__ tau_0,
             const float* __restrict__ tau_p,
             float* __restrict__ out)
{
    const int tid  = threadIdx.x;
    const int b    = blockIdx.x;
    const int wid  = tid >> 5;
    const int lane = tid & 31;

    float* out_mw = out;
    float* out_al = out + OUT_AL_OFF;

    __shared__ float s_mzz[ZDIM * ZDIM];
    __shared__ float2 s_c[NSTEPS];           // per-step (u_var, C2)
    __shared__ float2 s_red[K2_WARPS];
    __shared__ float s_ms[2];

    if (tid < ZDIM * ZDIM) s_mzz[tid] = g_mzz[tid];
    const float tau = tau_p[0];

    const int p0 = b * (K2_THREADS * 2) + tid;     // max 49663 < PDIM
    const int p1 = p0 + K2_THREADS;
    const bool v1 = (p1 < PDIM);

    // Per-thread register state from pre-reduced arrays (one load each).
    float W[ZDIM][2], Zt[ZDIM][2], lpi[ZDIM][2];
#pragma unroll
    for (int k = 0; k < ZDIM; k++) {
        Zt[k][0]  = g_ztr[k][p0];
        W[k][0]   = g_w0[k][p0];
        lpi[k][0] = __logf(pi[(size_t)k * PDIM + p0]);
        if (v1) {
            Zt[k][1]  = g_ztr[k][p1];
            W[k][1]   = g_w0[k][p1];
            lpi[k][1] = __logf(pi[(size_t)k * PDIM + p1]);
        } else { Zt[k][1] = 0.f; W[k][1] = 0.f; lpi[k][1] = 0.f; }
    }

    // Per-step constants hoisted off the step critical path:
    if (tid < NSTEPS) {
        int k = tid / LDIM, l = tid % LDIM;
        float Ezz  = g_mzz[k * ZDIM + k];
        float t0   = tau_0[l * ZDIM + k];
        float uv   = 1.f / (tau * Ezz + t0);
        float s2   = 1.f / (Ezz * tau);
        float s0i  = 1.f / t0;
        float C2   = 0.5f * (tau / Ezz) * (s0i / (s2 + s0i));
        s_c[k * LDIM + l] = make_float2(uv, C2);
    }
    __syncthreads();

#pragma unroll
    for (int k = 0; k < ZDIM; k++) {
        const float Ezz = s_mzz[k * ZDIM + k];
        float Rt[2], Wk[2];
#pragma unroll
        for (int e = 0; e < 2; e++) {
            float s = Zt[k][e];
#pragma unroll
            for (int j = 0; j < ZDIM; j++)
                s -= s_mzz[k * ZDIM + j] * W[j][e];
            Rt[e] = s + Ezz * W[k][e];
            Wk[e] = W[k][e];
        }

        // preload mw*al products for l=0 of this k
        float pw0, pw1;
        {
            size_t idx = (size_t)k * PDIM + p0;
            pw0 = mw_in[idx] * al_in[idx];
            pw1 = v1 ? mw_in[idx + K2_THREADS] * al_in[idx + K2_THREADS] : 0.f;
        }

        for (int l = 0; l < LDIM; l++) {
            const int step = k * LDIM + l;

            // issue raw loads for next l early (consumed at loop end)
            const int ln = (l + 1 < LDIM) ? l + 1 : l;
            const size_t nidx = (size_t)(ln * ZDIM + k) * PDIM + p0;
            float nm0 = mw_in[nidx], na0 = al_in[nidx];
            float nm1 = 0.f, na1 = 0.f;
            if (v1) { nm1 = mw_in[nidx + K2_THREADS]; na1 = al_in[nidx + K2_THREADS]; }

            const float2 uc    = s_c[step];
            const float u_var  = uc.x;
            const float C2     = uc.y;

            float Wkl0 = Wk[0] - pw0;
            float r0   = Rt[0] - Ezz * Wkl0;
            float lg0  = fmaf(C2 * r0, r0, lpi[k][0]);
            float Wkl1, r1, lg1;
            if (v1) {
                Wkl1 = Wk[1] - pw1;
                r1   = Rt[1] - Ezz * Wkl1;
                lg1  = fmaf(C2 * r1, r1, lpi[k][1]);
            } else { Wkl1 = 0.f; r1 = 0.f; lg1 = -1e30f; }

            // ---- warp-level online softmax reduce (m, s) ----
            float m = fmaxf(lg0, lg1);
            float s = __expf(lg0 - m) + __expf(lg1 - m);
#pragma unroll
            for (int o = 16; o > 0; o >>= 1) {
                float mo = __shfl_xor_sync(0xffffffffu, m, o);
                float so = __shfl_xor_sync(0xffffffffu, s, o);
                comb(m, s, mo, so);
            }
            // pre-barrier: per-thread softmax numerators vs the warp max
            const float e0 = __expf(lg0 - m);
            const float e1 = v1 ? __expf(lg1 - m) : 0.f;

            if (lane == 0) s_red[wid] = make_float2(m, s);
            __syncthreads();

            if (wid == 0) {
                float2 wv = (lane < K2_WARPS) ? s_red[lane] : make_float2(-1e30f, 0.f);
                float mb = wv.x, sb = wv.y;
#pragma unroll
                for (int o = 8; o > 0; o >>= 1) {
                    float mo = __shfl_xor_sync(0xffffffffu, mb, o);
                    float so = __shfl_xor_sync(0xffffffffu, sb, o);
                    comb(mb, sb, mo, so);
                }
                if (lane == 0) {
                    publish(&g_part[step][b], &g_cnt[step], mb, sb);
                    // single acquire point: lane0 polls the per-step counter
                    while (ld_acquire_u32(&g_cnt[step]) < K2_BLOCKS) { }
                }
                __syncwarp();

                // ---- grid combine: 2 parallel .cg reads/lane, then shuffles ----
                float2 v0 = __ldcg(&g_part[step][lane]);
                float2 v1g = (lane + 32 < K2_BLOCKS) ? __ldcg(&g_part[step][lane + 32])
                                                     : make_float2(-1e30f, 0.f);
                float ma = v0.x, sa = v0.y;
                comb(ma, sa, v1g.x, v1g.y);
#pragma unroll
                for (int o = 16; o > 0; o >>= 1) {
                    float mo = __shfl_xor_sync(0xffffffffu, ma, o);
                    float so = __shfl_xor_sync(0xffffffffu, sa, o);
                    comb(ma, sa, mo, so);
                }
                if (lane == 0) { s_ms[0] = ma; s_ms[1] = sa; }
            }
            __syncthreads();
            const float gm = s_ms[0];
            const float gs = s_ms[1];

            // ---- normalize via precomputed numerators, update Wk, store ----
            const float corr = __expf(m - gm) * __frcp_rn(gs);
            {
                float a  = e0 * corr;
                float um = tau * u_var * r0;
                Wk[0] = Wkl0 + um * a;
                size_t idx = (size_t)(l * ZDIM + k) * PDIM + p0;
                out_mw[idx] = um;
                out_al[idx] = a;
            }
            if (v1) {
                float a  = e1 * corr;
                float um = tau * u_var * r1;
                Wk[1] = Wkl1 + um * a;
                size_t idx = (size_t)(l * ZDIM + k) * PDIM + p1;
                out_mw[idx] = um;
                out_al[idx] = a;
            }

            pw0 = nm0 * na0;
            pw1 = nm1 * na1;
        }
        W[k][0] = Wk[0];
        W[k][1] = Wk[1];
    }
}

// ---------------------------------------------------------------------------
extern "C" void kernel_launch(void* const* d_in, const int* in_sizes, int n_in,
                              void* d_out, int out_size)
{
    (void)in_sizes; (void)n_in; (void)out_size;
    const float* data   = (const float*)d_in[0];
    const float* mean_z = (const float*)d_in[1];
    const float* var_z  = (const float*)d_in[2];
    const float* mean_w = (const float*)d_in[3];
    // d_in[4] = var_w (unused: vw output fully overwritten)
    const float* alpha  = (const float*)d_in[5];
    const float* tau_0  = (const float*)d_in[6];
    const float* pi     = (const float*)d_in[7];
    const float* tau    = (const float*)d_in[8];
    float* out = (float*)d_out;

    k1_ztr<<<K1_MAIN + 1, K1_THREADS>>>(data, mean_z, var_z, tau_0, tau,
                                        out + OUT_VW_OFF);
    k1b_reduce<<<K1B_BLOCKS, K1_THREADS>>>(mean_w, alpha);
    k2_loop<<<K2_BLOCKS, K2_THREADS>>>(mean_w, alpha, pi, tau_0, tau, out);
}

// round 15
// speedup vs baseline: 1.1800x; 1.0246x over previous
#include <cuda_runtime.h>
#include <cstdint>

#define NDIM 1000
#define PDIM 50000
#define ZDIM 10
#define LDIM 5

#define NSPLIT 8
#define NCHUNK (NDIM / NSPLIT)                        // 125
#define K1_THREADS 256
#define K1_PTILE (K1_THREADS * 4)                     // 1024
#define K1_PTILES ((PDIM + K1_PTILE - 1) / K1_PTILE)  // 49
#define K1_MAIN (K1_PTILES * NSPLIT)                  // 392
#define K1_DEPTH 6                                    // cp.async pipeline depth
#define K1_STAGES 8

#define K1B_BLOCKS (ZDIM * K1_PTILES)                 // 490

#define K2_BLOCKS 49
#define K2_THREADS 512
#define K2_WARPS (K2_THREADS / 32)                    // 16
#define NSTEPS (ZDIM * LDIM)                          // 50

#define OUT_VW_OFF (LDIM * ZDIM * PDIM)               // 250000
#define OUT_AL_OFF (OUT_VW_OFF + LDIM * ZDIM)         // 250050

// Static device scratch (no runtime allocation allowed)
__device__ __align__(16) float g_ztrp[NSPLIT][ZDIM][PDIM];   // 16 MB partials
__device__ __align__(16) float g_ztr[ZDIM][PDIM];            // reduced ZtR (2 MB)
__device__ __align__(16) float g_w0[ZDIM][PDIM];             // W0 = sum_l mw*al (2 MB)
__device__ float g_mzz[ZDIM * ZDIM];
__device__ __align__(128) float2 g_part[NSTEPS][64];         // per-step (m, s) per block
__device__ int g_cnt[NSTEPS];                                // per-step arrival counters

// ---- R3/R8-proven rendezvous primitives (acquire-based detection ONLY;
// ONE polling lane per CTA) ----
__device__ __forceinline__ void publish(float2* slot, int* cnt, float m, float s) {
    asm volatile("st.global.v2.f32 [%0], {%1, %2};" :: "l"(slot), "f"(m), "f"(s) : "memory");
    asm volatile("red.release.gpu.global.add.u32 [%0], 1;" :: "l"(cnt) : "memory");
}
__device__ __forceinline__ unsigned ld_acquire_u32(const int* p) {
    unsigned v;
    asm volatile("ld.acquire.gpu.global.u32 %0, [%1];" : "=r"(v) : "l"(p) : "memory");
    return v;
}

// ---- cp.async helpers ----
__device__ __forceinline__ void cp_async16(uint32_t smem_addr, const void* gptr) {
    asm volatile("cp.async.cg.shared.global [%0], [%1], 16;"
                 :: "r"(smem_addr), "l"(gptr) : "memory");
}
__device__ __forceinline__ void cp_commit() {
    asm volatile("cp.async.commit_group;" ::: "memory");
}
template <int N>
__device__ __forceinline__ void cp_wait() {
    asm volatile("cp.async.wait_group %0;" :: "n"(N) : "memory");
}

// one-exp online-softmax combine
__device__ __forceinline__ void comb(float& m, float& s, float mo, float so) {
    float d = m - mo;
    float e = __expf(-fabsf(d));
    bool ge = (d >= 0.f);
    s = ge ? fmaf(so, e, s) : fmaf(s, e, so);
    m = ge ? m : mo;
}

// ---------------------------------------------------------------------------
// Kernel 1: ZtR partials with a per-thread cp.async pipeline (depth 6).
// Each thread consumes ONLY its own 16B per row -> no block sync in loop.
// FMA order per accumulator unchanged vs R13 (bitwise-identical results).
// ---------------------------------------------------------------------------
__global__ __launch_bounds__(K1_THREADS)
void k1_ztr(const float* __restrict__ data,
            const float* __restrict__ mean_z,
            const float* __restrict__ var_z,
            const float* __restrict__ tau_0,
            const float* __restrict__ tau_p,
            float* __restrict__ out_vw)
{
    const int b = blockIdx.x;
    const int tid = threadIdx.x;

    if (b == K1_MAIN) {
        if (tid < NSTEPS) g_cnt[tid] = 0;
        __shared__ float s_mzz[ZDIM * ZDIM];
        if (tid < ZDIM * ZDIM) {
            int i = tid / ZDIM, j = tid % ZDIM;
            float s = 0.f;
            for (int n = 0; n < NDIM; n++)
                s += mean_z[n * ZDIM + i] * mean_z[n * ZDIM + j];
            s += (float)NDIM * var_z[i * ZDIM + j];
            s_mzz[tid] = s;
            g_mzz[tid] = s;
        }
        __syncthreads();
        if (tid < LDIM * ZDIM) {
            int l = tid / ZDIM, k = tid % ZDIM;
            float tau = tau_p[0];
            out_vw[tid] = 1.0f / (tau * s_mzz[k * ZDIM + k] + tau_0[l * ZDIM + k]);
        }
        return;
    }

    const int pt = b % K1_PTILES;
    const int c  = b / K1_PTILES;

    __shared__ __align__(16) float s_z[NCHUNK][12];
    __shared__ __align__(16) float s_d[K1_STAGES][K1_PTILE];   // 8 x 4KB

    for (int i = tid; i < NCHUNK * ZDIM; i += K1_THREADS) {
        int n = i / ZDIM, kk = i % ZDIM;
        s_z[n][kk] = mean_z[(c * NCHUNK + n) * ZDIM + kk];
    }
    __syncthreads();

    const int p0 = pt * K1_PTILE + tid * 4;
    if (p0 >= PDIM) return;   // per-thread cp.async groups: safe to drop out here

    float4 acc[ZDIM];
#pragma unroll
    for (int k = 0; k < ZDIM; k++) acc[k] = make_float4(0.f, 0.f, 0.f, 0.f);

    const float* dptr = data + (size_t)c * NCHUNK * PDIM + p0;
    const uint32_t sd0 = (uint32_t)__cvta_generic_to_shared(&s_d[0][tid * 4]);
    const uint32_t stage_bytes = K1_PTILE * 4;   // 4096

    // prologue: issue rows 0..DEPTH-1 (one 16B copy + commit per row)
#pragma unroll
    for (int n = 0; n < K1_DEPTH; n++) {
        cp_async16(sd0 + (n & 7) * stage_bytes, dptr + (size_t)n * PDIM);
        cp_commit();
    }

    int n = 0;
    for (; n + K1_DEPTH < NCHUNK; n++) {
        cp_async16(sd0 + ((n + K1_DEPTH) & 7) * stage_bytes,
                   dptr + (size_t)(n + K1_DEPTH) * PDIM);
        cp_commit();
        cp_wait<K1_DEPTH>();   // <=6 groups pending -> row n complete
        float4 d = *reinterpret_cast<const float4*>(&s_d[n & 7][tid * 4]);
        const float4* zr = reinterpret_cast<const float4*>(s_z[n]);
        float4 z0 = zr[0], z1 = zr[1], z2 = zr[2];
        float zk[ZDIM] = {z0.x, z0.y, z0.z, z0.w, z1.x, z1.y, z1.z, z1.w, z2.x, z2.y};
#pragma unroll
        for (int k = 0; k < ZDIM; k++) {
            acc[k].x = fmaf(zk[k], d.x, acc[k].x);
            acc[k].y = fmaf(zk[k], d.y, acc[k].y);
            acc[k].z = fmaf(zk[k], d.z, acc[k].z);
            acc[k].w = fmaf(zk[k], d.w, acc[k].w);
        }
    }
    cp_wait<0>();   // drain remaining rows
    for (; n < NCHUNK; n++) {
        float4 d = *reinterpret_cast<const float4*>(&s_d[n & 7][tid * 4]);
        const float4* zr = reinterpret_cast<const float4*>(s_z[n]);
        float4 z0 = zr[0], z1 = zr[1], z2 = zr[2];
        float zk[ZDIM] = {z0.x, z0.y, z0.z, z0.w, z1.x, z1.y, z1.z, z1.w, z2.x, z2.y};
#pragma unroll
        for (int k = 0; k < ZDIM; k++) {
            acc[k].x = fmaf(zk[k], d.x, acc[k].x);
            acc[k].y = fmaf(zk[k], d.y, acc[k].y);
            acc[k].z = fmaf(zk[k], d.z, acc[k].z);
            acc[k].w = fmaf(zk[k], d.w, acc[k].w);
        }
    }

#pragma unroll
    for (int k = 0; k < ZDIM; k++)
        *reinterpret_cast<float4*>(&g_ztrp[c][k][p0]) = acc[k];
}

// ---------------------------------------------------------------------------
// Kernel 1b: full-chip reduction — byte-identical to R13.
// ---------------------------------------------------------------------------
__global__ __launch_bounds__(K1_THREADS)
void k1b_reduce(const float* __restrict__ mw_in,
                const float* __restrict__ al_in)
{
    const int b   = blockIdx.x;                 // 0..489
    const int k   = b / K1_PTILES;
    const int pt  = b % K1_PTILES;
    const int p0  = pt * K1_PTILE + threadIdx.x * 4;
    if (p0 >= PDIM) return;

    float4 zt = make_float4(0.f, 0.f, 0.f, 0.f);
#pragma unroll
    for (int c = 0; c < NSPLIT; c++) {
        float4 v = *reinterpret_cast<const float4*>(&g_ztrp[c][k][p0]);
        zt.x += v.x; zt.y += v.y; zt.z += v.z; zt.w += v.w;
    }
    *reinterpret_cast<float4*>(&g_ztr[k][p0]) = zt;

    float4 w = make_float4(0.f, 0.f, 0.f, 0.f);
#pragma unroll
    for (int l = 0; l < LDIM; l++) {
        size_t idx = (size_t)(l * ZDIM + k) * PDIM + p0;
        float4 mwv = *reinterpret_cast<const float4*>(mw_in + idx);
        float4 alv = *reinterpret_cast<const float4*>(al_in + idx);
        w.x = fmaf(mwv.x, alv.x, w.x);
        w.y = fmaf(mwv.y, alv.y, w.y);
        w.z = fmaf(mwv.z, alv.z, w.z);
        w.w = fmaf(mwv.w, alv.w, w.w);
    }
    *reinterpret_cast<float4*>(&g_w0[k][p0]) = w;
}

// ---------------------------------------------------------------------------
// Kernel 2: persistent sweep — byte-identical to R13 (best measured).
// ---------------------------------------------------------------------------
__global__ __launch_bounds__(K2_THREADS)
void k2_loop(const float* __restrict__ mw_in,
             const float* __restrict__ al_in,
             const float* __restrict__ pi,
             const float* __restrict__ tau_0,
             const float* __restrict__ tau_p,
             float* __restrict__ out)
{
    const int tid  = threadIdx.x;
    const int b    = blockIdx.x;
    const int wid  = tid >> 5;
    const int lane = tid & 31;

    float* out_mw = out;
    float* out_al = out + OUT_AL_OFF;

    __shared__ float s_mzz[ZDIM * ZDIM];
    __shared__ float2 s_c[NSTEPS];
    __shared__ float2 s_red[K2_WARPS];
    __shared__ float s_ms[2];

    if (tid < ZDIM * ZDIM) s_mzz[tid] = g_mzz[tid];
    const float tau = tau_p[0];

    const int p0 = b * (K2_THREADS * 2) + tid;
    const int p1 = p0 + K2_THREADS;
    const bool v1 = (p1 < PDIM);

    float W[ZDIM][2], Zt[ZDIM][2], lpi[ZDIM][2];
#pragma unroll
    for (int k = 0; k < ZDIM; k++) {
        Zt[k][0]  = g_ztr[k][p0];
        W[k][0]   = g_w0[k][p0];
        lpi[k][0] = __logf(pi[(size_t)k * PDIM + p0]);
        if (v1) {
            Zt[k][1]  = g_ztr[k][p1];
            W[k][1]   = g_w0[k][p1];
            lpi[k][1] = __logf(pi[(size_t)k * PDIM + p1]);
        } else { Zt[k][1] = 0.f; W[k][1] = 0.f; lpi[k][1] = 0.f; }
    }

    if (tid < NSTEPS) {
        int k = tid / LDIM, l = tid % LDIM;
        float Ezz  = g_mzz[k * ZDIM + k];
        float t0   = tau_0[l * ZDIM + k];
        float uv   = 1.f / (tau * Ezz + t0);
        float s2   = 1.f / (Ezz * tau);
        float s0i  = 1.f / t0;
        float C2   = 0.5f * (tau / Ezz) * (s0i / (s2 + s0i));
        s_c[k * LDIM + l] = make_float2(uv, C2);
    }
    __syncthreads();

#pragma unroll
    for (int k = 0; k < ZDIM; k++) {
        const float Ezz = s_mzz[k * ZDIM + k];
        float Rt[2], Wk[2];
#pragma unroll
        for (int e = 0; e < 2; e++) {
            float s = Zt[k][e];
#pragma unroll
            for (int j = 0; j < ZDIM; j++)
                s -= s_mzz[k * ZDIM + j] * W[j][e];
            Rt[e] = s + Ezz * W[k][e];
            Wk[e] = W[k][e];
        }

        float pw0, pw1;
        {
            size_t idx = (size_t)k * PDIM + p0;
            pw0 = mw_in[idx] * al_in[idx];
            pw1 = v1 ? mw_in[idx + K2_THREADS] * al_in[idx + K2_THREADS] : 0.f;
        }

        for (int l = 0; l < LDIM; l++) {
            const int step = k * LDIM + l;

            const int ln = (l + 1 < LDIM) ? l + 1 : l;
            const size_t nidx = (size_t)(ln * ZDIM + k) * PDIM + p0;
            float nm0 = mw_in[nidx], na0 = al_in[nidx];
            float nm1 = 0.f, na1 = 0.f;
            if (v1) { nm1 = mw_in[nidx + K2_THREADS]; na1 = al_in[nidx + K2_THREADS]; }

            const float2 uc    = s_c[step];
            const float u_var  = uc.x;
            const float C2     = uc.y;

            float Wkl0 = Wk[0] - pw0;
            float r0   = Rt[0] - Ezz * Wkl0;
            float lg0  = fmaf(C2 * r0, r0, lpi[k][0]);
            float Wkl1, r1, lg1;
            if (v1) {
                Wkl1 = Wk[1] - pw1;
                r1   = Rt[1] - Ezz * Wkl1;
                lg1  = fmaf(C2 * r1, r1, lpi[k][1]);
            } else { Wkl1 = 0.f; r1 = 0.f; lg1 = -1e30f; }

            float m = fmaxf(lg0, lg1);
            float s = __expf(lg0 - m) + __expf(lg1 - m);
#pragma unroll
            for (int o = 16; o > 0; o >>= 1) {
                float mo = __shfl_xor_sync(0xffffffffu, m, o);
                float so = __shfl_xor_sync(0xffffffffu, s, o);
                comb(m, s, mo, so);
            }
            const float e0 = __expf(lg0 - m);
            const float e1 = v1 ? __expf(lg1 - m) : 0.f;

            if (lane == 0) s_red[wid] = make_float2(m, s);
            __syncthreads();

            if (wid == 0) {
                float2 wv = (lane < K2_WARPS) ? s_red[lane] : make_float2(-1e30f, 0.f);
                float mb = wv.x, sb = wv.y;
#pragma unroll
                for (int o = 8; o > 0; o >>= 1) {
                    float mo = __shfl_xor_sync(0xffffffffu, mb, o);
                    float so = __shfl_xor_sync(0xffffffffu, sb, o);
                    comb(mb, sb, mo, so);
                }
                if (lane == 0) {
                    publish(&g_part[step][b], &g_cnt[step], mb, sb);
                    while (ld_acquire_u32(&g_cnt[step]) < K2_BLOCKS) { }
                }
                __syncwarp();

                float2 v0 = __ldcg(&g_part[step][lane]);
                float2 v1g = (lane + 32 < K2_BLOCKS) ? __ldcg(&g_part[step][lane + 32])
                                                     : make_float2(-1e30f, 0.f);
                float ma = v0.x, sa = v0.y;
                comb(ma, sa, v1g.x, v1g.y);
#pragma unroll
                for (int o = 16; o > 0; o >>= 1) {
                    float mo = __shfl_xor_sync(0xffffffffu, ma, o);
                    float so = __shfl_xor_sync(0xffffffffu, sa, o);
                    comb(ma, sa, mo, so);
                }
                if (lane == 0) { s_ms[0] = ma; s_ms[1] = sa; }
            }
            __syncthreads();
            const float gm = s_ms[0];
            const float gs = s_ms[1];

            const float corr = __expf(m - gm) * __frcp_rn(gs);
            {
                float a  = e0 * corr;
                float um = tau * u_var * r0;
                Wk[0] = Wkl0 + um * a;
                size_t idx = (size_t)(l * ZDIM + k) * PDIM + p0;
                out_mw[idx] = um;
                out_al[idx] = a;
            }
            if (v1) {
                float a  = e1 * corr;
                float um = tau * u_var * r1;
                Wk[1] = Wkl1 + um * a;
                size_t idx = (size_t)(l * ZDIM + k) * PDIM + p1;
                out_mw[idx] = um;
                out_al[idx] = a;
            }

            pw0 = nm0 * na0;
            pw1 = nm1 * na1;
        }
        W[k][0] = Wk[0];
        W[k][1] = Wk[1];
    }
}

// ---------------------------------------------------------------------------
extern "C" void kernel_launch(void* const* d_in, const int* in_sizes, int n_in,
                              void* d_out, int out_size)
{
    (void)in_sizes; (void)n_in; (void)out_size;
    const float* data   = (const float*)d_in[0];
    const float* mean_z = (const float*)d_in[1];
    const float* var_z  = (const float*)d_in[2];
    const float* mean_w = (const float*)d_in[3];
    // d_in[4] = var_w (unused: vw output fully overwritten)
    const float* alpha  = (const float*)d_in[5];
    const float* tau_0  = (const float*)d_in[6];
    const float* pi     = (const float*)d_in[7];
    const float* tau    = (const float*)d_in[8];
    float* out = (float*)d_out;

    k1_ztr<<<K1_MAIN + 1, K1_THREADS>>>(data, mean_z, var_z, tau_0, tau,
                                        out + OUT_VW_OFF);
    k1b_reduce<<<K1B_BLOCKS, K1_THREADS>>>(mean_w, alpha);
    k2_loop<<<K2_BLOCKS, K2_THREADS>>>(mean_w, alpha, pi, tau_0, tau, out);
}

// round 16
// speedup vs baseline: 1.1878x; 1.0066x over previous
#include <cuda_runtime.h>
#include <cstdint>

#define NDIM 1000
#define PDIM 50000
#define ZDIM 10
#define LDIM 5

#define NSPLIT 8
#define NCHUNK (NDIM / NSPLIT)                        // 125
#define K1_THREADS 256
#define K1_PTILE (K1_THREADS * 4)                     // 1024
#define K1_PTILES ((PDIM + K1_PTILE - 1) / K1_PTILE)  // 49
#define K1_MAIN (K1_PTILES * NSPLIT)                  // 392
#define K1_DEPTH 6                                    // cp.async pipeline depth
#define K1_STAGES 8

#define K1B_BLOCKS (ZDIM * K1_PTILES)                 // 490

#define K2_BLOCKS 49
#define K2_THREADS 512
#define K2_WARPS (K2_THREADS / 32)                    // 16
#define NSTEPS (ZDIM * LDIM)                          // 50

#define OUT_VW_OFF (LDIM * ZDIM * PDIM)               // 250000
#define OUT_AL_OFF (OUT_VW_OFF + LDIM * ZDIM)         // 250050

// Static device scratch (no runtime allocation allowed)
__device__ __align__(16) float g_ztrp[NSPLIT][ZDIM][PDIM];   // 16 MB partials
__device__ __align__(16) float g_ztr[ZDIM][PDIM];            // reduced ZtR (2 MB)
__device__ __align__(16) float g_w0[ZDIM][PDIM];             // W0 = sum_l mw*al (2 MB)
__device__ float g_mzz[ZDIM * ZDIM];
__device__ __align__(128) float2 g_part[NSTEPS][64];         // per-step (m, s) per block
__device__ int g_cnt[NSTEPS];                                // per-step arrival counters

// ---- R3/R8-proven rendezvous primitives ----
__device__ __forceinline__ void publish(float2* slot, int* cnt, float m, float s) {
    asm volatile("st.global.v2.f32 [%0], {%1, %2};" :: "l"(slot), "f"(m), "f"(s) : "memory");
    asm volatile("red.release.gpu.global.add.u32 [%0], 1;" :: "l"(cnt) : "memory");
}
__device__ __forceinline__ unsigned ld_acquire_u32(const int* p) {
    unsigned v;
    asm volatile("ld.acquire.gpu.global.u32 %0, [%1];" : "=r"(v) : "l"(p) : "memory");
    return v;
}

// ---- cp.async helpers ----
__device__ __forceinline__ void cp_async16(uint32_t smem_addr, const void* gptr) {
    asm volatile("cp.async.cg.shared.global [%0], [%1], 16;"
                 :: "r"(smem_addr), "l"(gptr) : "memory");
}
__device__ __forceinline__ void cp_commit() {
    asm volatile("cp.async.commit_group;" ::: "memory");
}
template <int N>
__device__ __forceinline__ void cp_wait() {
    asm volatile("cp.async.wait_group %0;" :: "n"(N) : "memory");
}

// ---- packed fp32x2 FMA (Blackwell; ptxas never auto-fuses — PTX only) ----
// d = a * b + d, lane-wise over two packed fp32 -> bitwise == 2 scalar fmaf
__device__ __forceinline__ void fma_f32x2(unsigned long long& d,
                                          unsigned long long a,
                                          unsigned long long b) {
    asm("fma.rn.f32x2 %0, %1, %2, %3;" : "=l"(d) : "l"(a), "l"(b), "l"(d));
}

// one-exp online-softmax combine
__device__ __forceinline__ void comb(float& m, float& s, float mo, float so) {
    float d = m - mo;
    float e = __expf(-fabsf(d));
    bool ge = (d >= 0.f);
    s = ge ? fmaf(so, e, s) : fmaf(s, e, so);
    m = ge ? m : mo;
}

// ---------------------------------------------------------------------------
// Kernel 1: ZtR partials; cp.async depth-6 pipeline (R15) + packed f32x2 FMAs
// (20 FFMA2/row instead of 40 FFMA). mean_z staged DUPLICATED: s_z2[n] holds
// (z0,z0,z1,z1,...,z9,z9) so zk pairs load directly as u64 halves of LDS.128.
// Per-lane arithmetic order identical to R15 -> bitwise-identical ZtR.
// ---------------------------------------------------------------------------
__global__ __launch_bounds__(K1_THREADS)
void k1_ztr(const float* __restrict__ data,
            const float* __restrict__ mean_z,
            const float* __restrict__ var_z,
            const float* __restrict__ tau_0,
            const float* __restrict__ tau_p,
            float* __restrict__ out_vw)
{
    const int b = blockIdx.x;
    const int tid = threadIdx.x;

    if (b == K1_MAIN) {
        if (tid < NSTEPS) g_cnt[tid] = 0;
        __shared__ float s_mzz[ZDIM * ZDIM];
        if (tid < ZDIM * ZDIM) {
            int i = tid / ZDIM, j = tid % ZDIM;
            float s = 0.f;
            for (int n = 0; n < NDIM; n++)
                s += mean_z[n * ZDIM + i] * mean_z[n * ZDIM + j];
            s += (float)NDIM * var_z[i * ZDIM + j];
            s_mzz[tid] = s;
            g_mzz[tid] = s;
        }
        __syncthreads();
        if (tid < LDIM * ZDIM) {
            int l = tid / ZDIM, k = tid % ZDIM;
            float tau = tau_p[0];
            out_vw[tid] = 1.0f / (tau * s_mzz[k * ZDIM + k] + tau_0[l * ZDIM + k]);
        }
        return;
    }

    const int pt = b % K1_PTILES;
    const int c  = b / K1_PTILES;

    __shared__ __align__(16) float s_z2[NCHUNK][20];           // duplicated z pairs
    __shared__ __align__(16) float s_d[K1_STAGES][K1_PTILE];   // 8 x 4KB

    for (int i = tid; i < NCHUNK * ZDIM; i += K1_THREADS) {
        int n = i / ZDIM, kk = i % ZDIM;
        float z = mean_z[(c * NCHUNK + n) * ZDIM + kk];
        s_z2[n][2 * kk]     = z;
        s_z2[n][2 * kk + 1] = z;
    }
    __syncthreads();

    const int p0 = pt * K1_PTILE + tid * 4;
    if (p0 >= PDIM) return;   // per-thread cp.async groups: safe to drop out

    unsigned long long acc01[ZDIM], acc23[ZDIM];
#pragma unroll
    for (int k = 0; k < ZDIM; k++) { acc01[k] = 0ull; acc23[k] = 0ull; }

    const float* dptr = data + (size_t)c * NCHUNK * PDIM + p0;
    const uint32_t sd0 = (uint32_t)__cvta_generic_to_shared(&s_d[0][tid * 4]);
    const uint32_t stage_bytes = K1_PTILE * 4;   // 4096

#pragma unroll
    for (int n = 0; n < K1_DEPTH; n++) {
        cp_async16(sd0 + (n & 7) * stage_bytes, dptr + (size_t)n * PDIM);
        cp_commit();
    }

    int n = 0;
    for (; n + K1_DEPTH < NCHUNK; n++) {
        cp_async16(sd0 + ((n + K1_DEPTH) & 7) * stage_bytes,
                   dptr + (size_t)(n + K1_DEPTH) * PDIM);
        cp_commit();
        cp_wait<K1_DEPTH>();
        ulonglong2 dv = *reinterpret_cast<const ulonglong2*>(&s_d[n & 7][tid * 4]);
        const ulonglong2* zr = reinterpret_cast<const ulonglong2*>(s_z2[n]);
        ulonglong2 zp0 = zr[0], zp1 = zr[1], zp2 = zr[2], zp3 = zr[3], zp4 = zr[4];
        unsigned long long zk[ZDIM] = {zp0.x, zp0.y, zp1.x, zp1.y, zp2.x,
                                       zp2.y, zp3.x, zp3.y, zp4.x, zp4.y};
#pragma unroll
        for (int k = 0; k < ZDIM; k++) {
            fma_f32x2(acc01[k], zk[k], dv.x);
            fma_f32x2(acc23[k], zk[k], dv.y);
        }
    }
    cp_wait<0>();
    for (; n < NCHUNK; n++) {
        ulonglong2 dv = *reinterpret_cast<const ulonglong2*>(&s_d[n & 7][tid * 4]);
        const ulonglong2* zr = reinterpret_cast<const ulonglong2*>(s_z2[n]);
        ulonglong2 zp0 = zr[0], zp1 = zr[1], zp2 = zr[2], zp3 = zr[3], zp4 = zr[4];
        unsigned long long zk[ZDIM] = {zp0.x, zp0.y, zp1.x, zp1.y, zp2.x,
                                       zp2.y, zp3.x, zp3.y, zp4.x, zp4.y};
#pragma unroll
        for (int k = 0; k < ZDIM; k++) {
            fma_f32x2(acc01[k], zk[k], dv.x);
            fma_f32x2(acc23[k], zk[k], dv.y);
        }
    }

#pragma unroll
    for (int k = 0; k < ZDIM; k++) {
        ulonglong2 outv;
        outv.x = acc01[k];
        outv.y = acc23[k];
        *reinterpret_cast<ulonglong2*>(&g_ztrp[c][k][p0]) = outv;
    }
}

// ---------------------------------------------------------------------------
// Kernel 1b: full-chip reduction — byte-identical to R13/R15.
// ---------------------------------------------------------------------------
__global__ __launch_bounds__(K1_THREADS)
void k1b_reduce(const float* __restrict__ mw_in,
                const float* __restrict__ al_in)
{
    const int b   = blockIdx.x;                 // 0..489
    const int k   = b / K1_PTILES;
    const int pt  = b % K1_PTILES;
    const int p0  = pt * K1_PTILE + threadIdx.x * 4;
    if (p0 >= PDIM) return;

    float4 zt = make_float4(0.f, 0.f, 0.f, 0.f);
#pragma unroll
    for (int c = 0; c < NSPLIT; c++) {
        float4 v = *reinterpret_cast<const float4*>(&g_ztrp[c][k][p0]);
        zt.x += v.x; zt.y += v.y; zt.z += v.z; zt.w += v.w;
    }
    *reinterpret_cast<float4*>(&g_ztr[k][p0]) = zt;

    float4 w = make_float4(0.f, 0.f, 0.f, 0.f);
#pragma unroll
    for (int l = 0; l < LDIM; l++) {
        size_t idx = (size_t)(l * ZDIM + k) * PDIM + p0;
        float4 mwv = *reinterpret_cast<const float4*>(mw_in + idx);
        float4 alv = *reinterpret_cast<const float4*>(al_in + idx);
        w.x = fmaf(mwv.x, alv.x, w.x);
        w.y = fmaf(mwv.y, alv.y, w.y);
        w.z = fmaf(mwv.z, alv.z, w.z);
        w.w = fmaf(mwv.w, alv.w, w.w);
    }
    *reinterpret_cast<float4*>(&g_w0[k][p0]) = w;
}

// ---------------------------------------------------------------------------
// Kernel 2: persistent sweep — byte-identical to R13/R15 (best measured).
// ---------------------------------------------------------------------------
__global__ __launch_bounds__(K2_THREADS)
void k2_loop(const float* __restrict__ mw_in,
             const float* __restrict__ al_in,
             const float* __restrict__ pi,
             const float* __restrict__ tau_0,
             const float* __restrict__ tau_p,
             float* __restrict__ out)
{
    const int tid  = threadIdx.x;
    const int b    = blockIdx.x;
    const int wid  = tid >> 5;
    const int lane = tid & 31;

    float* out_mw = out;
    float* out_al = out + OUT_AL_OFF;

    __shared__ float s_mzz[ZDIM * ZDIM];
    __shared__ float2 s_c[NSTEPS];
    __shared__ float2 s_red[K2_WARPS];
    __shared__ float s_ms[2];

    if (tid < ZDIM * ZDIM) s_mzz[tid] = g_mzz[tid];
    const float tau = tau_p[0];

    const int p0 = b * (K2_THREADS * 2) + tid;
    const int p1 = p0 + K2_THREADS;
    const bool v1 = (p1 < PDIM);

    float W[ZDIM][2], Zt[ZDIM][2], lpi[ZDIM][2];
#pragma unroll
    for (int k = 0; k < ZDIM; k++) {
        Zt[k][0]  = g_ztr[k][p0];
        W[k][0]   = g_w0[k][p0];
        lpi[k][0] = __logf(pi[(size_t)k * PDIM + p0]);
        if (v1) {
            Zt[k][1]  = g_ztr[k][p1];
            W[k][1]   = g_w0[k][p1];
            lpi[k][1] = __logf(pi[(size_t)k * PDIM + p1]);
        } else { Zt[k][1] = 0.f; W[k][1] = 0.f; lpi[k][1] = 0.f; }
    }

    if (tid < NSTEPS) {
        int k = tid / LDIM, l = tid % LDIM;
        float Ezz  = g_mzz[k * ZDIM + k];
        float t0   = tau_0[l * ZDIM + k];
        float uv   = 1.f / (tau * Ezz + t0);
        float s2   = 1.f / (Ezz * tau);
        float s0i  = 1.f / t0;
        float C2   = 0.5f * (tau / Ezz) * (s0i / (s2 + s0i));
        s_c[k * LDIM + l] = make_float2(uv, C2);
    }
    __syncthreads();

#pragma unroll
    for (int k = 0; k < ZDIM; k++) {
        const float Ezz = s_mzz[k * ZDIM + k];
        float Rt[2], Wk[2];
#pragma unroll
        for (int e = 0; e < 2; e++) {
            float s = Zt[k][e];
#pragma unroll
            for (int j = 0; j < ZDIM; j++)
                s -= s_mzz[k * ZDIM + j] * W[j][e];
            Rt[e] = s + Ezz * W[k][e];
            Wk[e] = W[k][e];
        }

        float pw0, pw1;
        {
            size_t idx = (size_t)k * PDIM + p0;
            pw0 = mw_in[idx] * al_in[idx];
            pw1 = v1 ? mw_in[idx + K2_THREADS] * al_in[idx + K2_THREADS] : 0.f;
        }

        for (int l = 0; l < LDIM; l++) {
            const int step = k * LDIM + l;

            const int ln = (l + 1 < LDIM) ? l + 1 : l;
            const size_t nidx = (size_t)(ln * ZDIM + k) * PDIM + p0;
            float nm0 = mw_in[nidx], na0 = al_in[nidx];
            float nm1 = 0.f, na1 = 0.f;
            if (v1) { nm1 = mw_in[nidx + K2_THREADS]; na1 = al_in[nidx + K2_THREADS]; }

            const float2 uc    = s_c[step];
            const float u_var  = uc.x;
            const float C2     = uc.y;

            float Wkl0 = Wk[0] - pw0;
            float r0   = Rt[0] - Ezz * Wkl0;
            float lg0  = fmaf(C2 * r0, r0, lpi[k][0]);
            float Wkl1, r1, lg1;
            if (v1) {
                Wkl1 = Wk[1] - pw1;
                r1   = Rt[1] - Ezz * Wkl1;
                lg1  = fmaf(C2 * r1, r1, lpi[k][1]);
            } else { Wkl1 = 0.f; r1 = 0.f; lg1 = -1e30f; }

            float m = fmaxf(lg0, lg1);
            float s = __expf(lg0 - m) + __expf(lg1 - m);
#pragma unroll
            for (int o = 16; o > 0; o >>= 1) {
                float mo = __shfl_xor_sync(0xffffffffu, m, o);
                float so = __shfl_xor_sync(0xffffffffu, s, o);
                comb(m, s, mo, so);
            }
            const float e0 = __expf(lg0 - m);
            const float e1 = v1 ? __expf(lg1 - m) : 0.f;

            if (lane == 0) s_red[wid] = make_float2(m, s);
            __syncthreads();

            if (wid == 0) {
                float2 wv = (lane < K2_WARPS) ? s_red[lane] : make_float2(-1e30f, 0.f);
                float mb = wv.x, sb = wv.y;
#pragma unroll
                for (int o = 8; o > 0; o >>= 1) {
                    float mo = __shfl_xor_sync(0xffffffffu, mb, o);
                    float so = __shfl_xor_sync(0xffffffffu, sb, o);
                    comb(mb, sb, mo, so);
                }
                if (lane == 0) {
                    publish(&g_part[step][b], &g_cnt[step], mb, sb);
                    while (ld_acquire_u32(&g_cnt[step]) < K2_BLOCKS) { }
                }
                __syncwarp();

                float2 v0 = __ldcg(&g_part[step][lane]);
                float2 v1g = (lane + 32 < K2_BLOCKS) ? __ldcg(&g_part[step][lane + 32])
                                                     : make_float2(-1e30f, 0.f);
                float ma = v0.x, sa = v0.y;
                comb(ma, sa, v1g.x, v1g.y);
#pragma unroll
                for (int o = 16; o > 0; o >>= 1) {
                    float mo = __shfl_xor_sync(0xffffffffu, ma, o);
                    float so = __shfl_xor_sync(0xffffffffu, sa, o);
                    comb(ma, sa, mo, so);
                }
                if (lane == 0) { s_ms[0] = ma; s_ms[1] = sa; }
            }
            __syncthreads();
            const float gm = s_ms[0];
            const float gs = s_ms[1];

            const float corr = __expf(m - gm) * __frcp_rn(gs);
            {
                float a  = e0 * corr;
                float um = tau * u_var * r0;
                Wk[0] = Wkl0 + um * a;
                size_t idx = (size_t)(l * ZDIM + k) * PDIM + p0;
                out_mw[idx] = um;
                out_al[idx] = a;
            }
            if (v1) {
                float a  = e1 * corr;
                float um = tau * u_var * r1;
                Wk[1] = Wkl1 + um * a;
                size_t idx = (size_t)(l * ZDIM + k) * PDIM + p1;
                out_mw[idx] = um;
                out_al[idx] = a;
            }

            pw0 = nm0 * na0;
            pw1 = nm1 * na1;
        }
        W[k][0] = Wk[0];
        W[k][1] = Wk[1];
    }
}

// ---------------------------------------------------------------------------
extern "C" void kernel_launch(void* const* d_in, const int* in_sizes, int n_in,
                              void* d_out, int out_size)
{
    (void)in_sizes; (void)n_in; (void)out_size;
    const float* data   = (const float*)d_in[0];
    const float* mean_z = (const float*)d_in[1];
    const float* var_z  = (const float*)d_in[2];
    const float* mean_w = (const float*)d_in[3];
    // d_in[4] = var_w (unused: vw output fully overwritten)
    const float* alpha  = (const float*)d_in[5];
    const float* tau_0  = (const float*)d_in[6];
    const float* pi     = (const float*)d_in[7];
    const float* tau    = (const float*)d_in[8];
    float* out = (float*)d_out;

    k1_ztr<<<K1_MAIN + 1, K1_THREADS>>>(data, mean_z, var_z, tau_0, tau,
                                        out + OUT_VW_OFF);
    k1b_reduce<<<K1B_BLOCKS, K1_THREADS>>>(mean_w, alpha);
    k2_loop<<<K2_BLOCKS, K2_THREADS>>>(mean_w, alpha, pi, tau_0, tau, out);
}

// round 17
// speedup vs baseline: 1.1992x; 1.0096x over previous
#include <cuda_runtime.h>
#include <cstdint>

#define NDIM 1000
#define PDIM 50000
#define ZDIM 10
#define LDIM 5

// k1: 9 n-chunks (111/112 rows) x 49 p-tiles = 441 main + 1 aux = 442 blocks
// = almost exactly 3 CTAs/SM (146 SMs x 3 + 2 x 2), fully co-resident in one
// balanced wave (resources allow 3: 70 regs, ~41KB smem per CTA).
#define NSPLIT 9
#define NCHUNK_MAX 112
#define K1_THREADS 256
#define K1_PTILE (K1_THREADS * 4)                     // 1024
#define K1_PTILES ((PDIM + K1_PTILE - 1) / K1_PTILE)  // 49
#define K1_MAIN (K1_PTILES * NSPLIT)                  // 441
#define K1_DEPTH 6                                    // cp.async pipeline depth
#define K1_STAGES 8

#define K1B_BLOCKS (ZDIM * K1_PTILES)                 // 490

#define K2_BLOCKS 49
#define K2_THREADS 512
#define K2_WARPS (K2_THREADS / 32)                    // 16
#define NSTEPS (ZDIM * LDIM)                          // 50

#define OUT_VW_OFF (LDIM * ZDIM * PDIM)               // 250000
#define OUT_AL_OFF (OUT_VW_OFF + LDIM * ZDIM)         // 250050

// Static device scratch (no runtime allocation allowed)
__device__ __align__(16) float g_ztrp[NSPLIT][ZDIM][PDIM];   // 18 MB partials
__device__ __align__(16) float g_ztr[ZDIM][PDIM];            // reduced ZtR (2 MB)
__device__ __align__(16) float g_w0[ZDIM][PDIM];             // W0 = sum_l mw*al (2 MB)
__device__ float g_mzz[ZDIM * ZDIM];
__device__ __align__(128) float2 g_part[NSTEPS][64];         // per-step (m, s) per block
__device__ int g_cnt[NSTEPS];                                // per-step arrival counters

// ---- R3/R8-proven rendezvous primitives ----
__device__ __forceinline__ void publish(float2* slot, int* cnt, float m, float s) {
    asm volatile("st.global.v2.f32 [%0], {%1, %2};" :: "l"(slot), "f"(m), "f"(s) : "memory");
    asm volatile("red.release.gpu.global.add.u32 [%0], 1;" :: "l"(cnt) : "memory");
}
__device__ __forceinline__ unsigned ld_acquire_u32(const int* p) {
    unsigned v;
    asm volatile("ld.acquire.gpu.global.u32 %0, [%1];" : "=r"(v) : "l"(p) : "memory");
    return v;
}

// ---- cp.async helpers ----
__device__ __forceinline__ void cp_async16(uint32_t smem_addr, const void* gptr) {
    asm volatile("cp.async.cg.shared.global [%0], [%1], 16;"
                 :: "r"(smem_addr), "l"(gptr) : "memory");
}
__device__ __forceinline__ void cp_commit() {
    asm volatile("cp.async.commit_group;" ::: "memory");
}
template <int N>
__device__ __forceinline__ void cp_wait() {
    asm volatile("cp.async.wait_group %0;" :: "n"(N) : "memory");
}

// ---- packed fp32x2 FMA (Blackwell; PTX only — ptxas never auto-fuses) ----
__device__ __forceinline__ void fma_f32x2(unsigned long long& d,
                                          unsigned long long a,
                                          unsigned long long b) {
    asm("fma.rn.f32x2 %0, %1, %2, %3;" : "=l"(d) : "l"(a), "l"(b), "l"(d));
}

// one-exp online-softmax combine
__device__ __forceinline__ void comb(float& m, float& s, float mo, float so) {
    float d = m - mo;
    float e = __expf(-fabsf(d));
    bool ge = (d >= 0.f);
    s = ge ? fmaf(so, e, s) : fmaf(s, e, so);
    m = ge ? m : mo;
}

// ---------------------------------------------------------------------------
// Kernel 1: ZtR partials; cp.async depth-6 pipeline + packed f32x2 FMAs.
// 9 uneven n-chunks via integer split; inner body identical to R16.
// ---------------------------------------------------------------------------
__global__ __launch_bounds__(K1_THREADS)
void k1_ztr(const float* __restrict__ data,
            const float* __restrict__ mean_z,
            const float* __restrict__ var_z,
            const float* __restrict__ tau_0,
            const float* __restrict__ tau_p,
            float* __restrict__ out_vw)
{
    const int b = blockIdx.x;
    const int tid = threadIdx.x;

    if (b == K1_MAIN) {
        if (tid < NSTEPS) g_cnt[tid] = 0;
        __shared__ float s_mzz[ZDIM * ZDIM];
        if (tid < ZDIM * ZDIM) {
            int i = tid / ZDIM, j = tid % ZDIM;
            float s = 0.f;
            for (int n = 0; n < NDIM; n++)
                s += mean_z[n * ZDIM + i] * mean_z[n * ZDIM + j];
            s += (float)NDIM * var_z[i * ZDIM + j];
            s_mzz[tid] = s;
            g_mzz[tid] = s;
        }
        __syncthreads();
        if (tid < LDIM * ZDIM) {
            int l = tid / ZDIM, k = tid % ZDIM;
            float tau = tau_p[0];
            out_vw[tid] = 1.0f / (tau * s_mzz[k * ZDIM + k] + tau_0[l * ZDIM + k]);
        }
        return;
    }

    const int pt = b % K1_PTILES;
    const int c  = b / K1_PTILES;
    // integer split: chunk c covers rows [c*N/9, (c+1)*N/9)  (111 or 112 rows)
    const int row0 = (c * NDIM) / NSPLIT;
    const int len  = ((c + 1) * NDIM) / NSPLIT - row0;

    __shared__ __align__(16) float s_z2[NCHUNK_MAX][20];       // duplicated z pairs
    __shared__ __align__(16) float s_d[K1_STAGES][K1_PTILE];   // 8 x 4KB

    for (int i = tid; i < len * ZDIM; i += K1_THREADS) {
        int n = i / ZDIM, kk = i % ZDIM;
        float z = mean_z[(row0 + n) * ZDIM + kk];
        s_z2[n][2 * kk]     = z;
        s_z2[n][2 * kk + 1] = z;
    }
    __syncthreads();

    const int p0 = pt * K1_PTILE + tid * 4;
    if (p0 >= PDIM) return;   // per-thread cp.async groups: safe to drop out

    unsigned long long acc01[ZDIM], acc23[ZDIM];
#pragma unroll
    for (int k = 0; k < ZDIM; k++) { acc01[k] = 0ull; acc23[k] = 0ull; }

    const float* dptr = data + (size_t)row0 * PDIM + p0;
    const uint32_t sd0 = (uint32_t)__cvta_generic_to_shared(&s_d[0][tid * 4]);
    const uint32_t stage_bytes = K1_PTILE * 4;   // 4096

#pragma unroll
    for (int n = 0; n < K1_DEPTH; n++) {
        cp_async16(sd0 + (n & 7) * stage_bytes, dptr + (size_t)n * PDIM);
        cp_commit();
    }

    int n = 0;
    for (; n + K1_DEPTH < len; n++) {
        cp_async16(sd0 + ((n + K1_DEPTH) & 7) * stage_bytes,
                   dptr + (size_t)(n + K1_DEPTH) * PDIM);
        cp_commit();
        cp_wait<K1_DEPTH>();
        ulonglong2 dv = *reinterpret_cast<const ulonglong2*>(&s_d[n & 7][tid * 4]);
        const ulonglong2* zr = reinterpret_cast<const ulonglong2*>(s_z2[n]);
        ulonglong2 zp0 = zr[0], zp1 = zr[1], zp2 = zr[2], zp3 = zr[3], zp4 = zr[4];
        unsigned long long zk[ZDIM] = {zp0.x, zp0.y, zp1.x, zp1.y, zp2.x,
                                       zp2.y, zp3.x, zp3.y, zp4.x, zp4.y};
#pragma unroll
        for (int k = 0; k < ZDIM; k++) {
            fma_f32x2(acc01[k], zk[k], dv.x);
            fma_f32x2(acc23[k], zk[k], dv.y);
        }
    }
    cp_wait<0>();
    for (; n < len; n++) {
        ulonglong2 dv = *reinterpret_cast<const ulonglong2*>(&s_d[n & 7][tid * 4]);
        const ulonglong2* zr = reinterpret_cast<const ulonglong2*>(s_z2[n]);
        ulonglong2 zp0 = zr[0], zp1 = zr[1], zp2 = zr[2], zp3 = zr[3], zp4 = zr[4];
        unsigned long long zk[ZDIM] = {zp0.x, zp0.y, zp1.x, zp1.y, zp2.x,
                                       zp2.y, zp3.x, zp3.y, zp4.x, zp4.y};
#pragma unroll
        for (int k = 0; k < ZDIM; k++) {
            fma_f32x2(acc01[k], zk[k], dv.x);
            fma_f32x2(acc23[k], zk[k], dv.y);
        }
    }

#pragma unroll
    for (int k = 0; k < ZDIM; k++) {
        ulonglong2 outv;
        outv.x = acc01[k];
        outv.y = acc23[k];
        *reinterpret_cast<ulonglong2*>(&g_ztrp[c][k][p0]) = outv;
    }
}

// ---------------------------------------------------------------------------
// Kernel 1b: full-chip reduction (9 partials now).
// ---------------------------------------------------------------------------
__global__ __launch_bounds__(K1_THREADS)
void k1b_reduce(const float* __restrict__ mw_in,
                const float* __restrict__ al_in)
{
    const int b   = blockIdx.x;                 // 0..489
    const int k   = b / K1_PTILES;
    const int pt  = b % K1_PTILES;
    const int p0  = pt * K1_PTILE + threadIdx.x * 4;
    if (p0 >= PDIM) return;

    float4 zt = make_float4(0.f, 0.f, 0.f, 0.f);
#pragma unroll
    for (int c = 0; c < NSPLIT; c++) {
        float4 v = *reinterpret_cast<const float4*>(&g_ztrp[c][k][p0]);
        zt.x += v.x; zt.y += v.y; zt.z += v.z; zt.w += v.w;
    }
    *reinterpret_cast<float4*>(&g_ztr[k][p0]) = zt;

    float4 w = make_float4(0.f, 0.f, 0.f, 0.f);
#pragma unroll
    for (int l = 0; l < LDIM; l++) {
        size_t idx = (size_t)(l * ZDIM + k) * PDIM + p0;
        float4 mwv = *reinterpret_cast<const float4*>(mw_in + idx);
        float4 alv = *reinterpret_cast<const float4*>(al_in + idx);
        w.x = fmaf(mwv.x, alv.x, w.x);
        w.y = fmaf(mwv.y, alv.y, w.y);
        w.z = fmaf(mwv.z, alv.z, w.z);
        w.w = fmaf(mwv.w, alv.w, w.w);
    }
    *reinterpret_cast<float4*>(&g_w0[k][p0]) = w;
}

// ---------------------------------------------------------------------------
// Kernel 2: persistent sweep — byte-identical to R13/R15/R16 (best measured).
// ---------------------------------------------------------------------------
__global__ __launch_bounds__(K2_THREADS)
void k2_loop(const float* __restrict__ mw_in,
             const float* __restrict__ al_in,
             const float* __restrict__ pi,
             const float* __restrict__ tau_0,
             const float* __restrict__ tau_p,
             float* __restrict__ out)
{
    const int tid  = threadIdx.x;
    const int b    = blockIdx.x;
    const int wid  = tid >> 5;
    const int lane = tid & 31;

    float* out_mw = out;
    float* out_al = out + OUT_AL_OFF;

    __shared__ float s_mzz[ZDIM * ZDIM];
    __shared__ float2 s_c[NSTEPS];
    __shared__ float2 s_red[K2_WARPS];
    __shared__ float s_ms[2];

    if (tid < ZDIM * ZDIM) s_mzz[tid] = g_mzz[tid];
    const float tau = tau_p[0];

    const int p0 = b * (K2_THREADS * 2) + tid;
    const int p1 = p0 + K2_THREADS;
    const bool v1 = (p1 < PDIM);

    float W[ZDIM][2], Zt[ZDIM][2], lpi[ZDIM][2];
#pragma unroll
    for (int k = 0; k < ZDIM; k++) {
        Zt[k][0]  = g_ztr[k][p0];
        W[k][0]   = g_w0[k][p0];
        lpi[k][0] = __logf(pi[(size_t)k * PDIM + p0]);
        if (v1) {
            Zt[k][1]  = g_ztr[k][p1];
            W[k][1]   = g_w0[k][p1];
            lpi[k][1] = __logf(pi[(size_t)k * PDIM + p1]);
        } else { Zt[k][1] = 0.f; W[k][1] = 0.f; lpi[k][1] = 0.f; }
    }

    if (tid < NSTEPS) {
        int k = tid / LDIM, l = tid % LDIM;
        float Ezz  = g_mzz[k * ZDIM + k];
        float t0   = tau_0[l * ZDIM + k];
        float uv   = 1.f / (tau * Ezz + t0);
        float s2   = 1.f / (Ezz * tau);
        float s0i  = 1.f / t0;
        float C2   = 0.5f * (tau / Ezz) * (s0i / (s2 + s0i));
        s_c[k * LDIM + l] = make_float2(uv, C2);
    }
    __syncthreads();

#pragma unroll
    for (int k = 0; k < ZDIM; k++) {
        const float Ezz = s_mzz[k * ZDIM + k];
        float Rt[2], Wk[2];
#pragma unroll
        for (int e = 0; e < 2; e++) {
            float s = Zt[k][e];
#pragma unroll
            for (int j = 0; j < ZDIM; j++)
                s -= s_mzz[k * ZDIM + j] * W[j][e];
            Rt[e] = s + Ezz * W[k][e];
            Wk[e] = W[k][e];
        }

        float pw0, pw1;
        {
            size_t idx = (size_t)k * PDIM + p0;
            pw0 = mw_in[idx] * al_in[idx];
            pw1 = v1 ? mw_in[idx + K2_THREADS] * al_in[idx + K2_THREADS] : 0.f;
        }

        for (int l = 0; l < LDIM; l++) {
            const int step = k * LDIM + l;

            const int ln = (l + 1 < LDIM) ? l + 1 : l;
            const size_t nidx = (size_t)(ln * ZDIM + k) * PDIM + p0;
            float nm0 = mw_in[nidx], na0 = al_in[nidx];
            float nm1 = 0.f, na1 = 0.f;
            if (v1) { nm1 = mw_in[nidx + K2_THREADS]; na1 = al_in[nidx + K2_THREADS]; }

            const float2 uc    = s_c[step];
            const float u_var  = uc.x;
            const float C2     = uc.y;

            float Wkl0 = Wk[0] - pw0;
            float r0   = Rt[0] - Ezz * Wkl0;
            float lg0  = fmaf(C2 * r0, r0, lpi[k][0]);
            float Wkl1, r1, lg1;
            if (v1) {
                Wkl1 = Wk[1] - pw1;
                r1   = Rt[1] - Ezz * Wkl1;
                lg1  = fmaf(C2 * r1, r1, lpi[k][1]);
            } else { Wkl1 = 0.f; r1 = 0.f; lg1 = -1e30f; }

            float m = fmaxf(lg0, lg1);
            float s = __expf(lg0 - m) + __expf(lg1 - m);
#pragma unroll
            for (int o = 16; o > 0; o >>= 1) {
                float mo = __shfl_xor_sync(0xffffffffu, m, o);
                float so = __shfl_xor_sync(0xffffffffu, s, o);
                comb(m, s, mo, so);
            }
            const float e0 = __expf(lg0 - m);
            const float e1 = v1 ? __expf(lg1 - m) : 0.f;

            if (lane == 0) s_red[wid] = make_float2(m, s);
            __syncthreads();

            if (wid == 0) {
                float2 wv = (lane < K2_WARPS) ? s_red[lane] : make_float2(-1e30f, 0.f);
                float mb = wv.x, sb = wv.y;
#pragma unroll
                for (int o = 8; o > 0; o >>= 1) {
                    float mo = __shfl_xor_sync(0xffffffffu, mb, o);
                    float so = __shfl_xor_sync(0xffffffffu, sb, o);
                    comb(mb, sb, mo, so);
                }
                if (lane == 0) {
                    publish(&g_part[step][b], &g_cnt[step], mb, sb);
                    while (ld_acquire_u32(&g_cnt[step]) < K2_BLOCKS) { }
                }
                __syncwarp();

                float2 v0 = __ldcg(&g_part[step][lane]);
                float2 v1g = (lane + 32 < K2_BLOCKS) ? __ldcg(&g_part[step][lane + 32])
                                                     : make_float2(-1e30f, 0.f);
                float ma = v0.x, sa = v0.y;
                comb(ma, sa, v1g.x, v1g.y);
#pragma unroll
                for (int o = 16; o > 0; o >>= 1) {
                    float mo = __shfl_xor_sync(0xffffffffu, ma, o);
                    float so = __shfl_xor_sync(0xffffffffu, sa, o);
                    comb(ma, sa, mo, so);
                }
                if (lane == 0) { s_ms[0] = ma; s_ms[1] = sa; }
            }
            __syncthreads();
            const float gm = s_ms[0];
            const float gs = s_ms[1];

            const float corr = __expf(m - gm) * __frcp_rn(gs);
            {
                float a  = e0 * corr;
                float um = tau * u_var * r0;
                Wk[0] = Wkl0 + um * a;
                size_t idx = (size_t)(l * ZDIM + k) * PDIM + p0;
                out_mw[idx] = um;
                out_al[idx] = a;
            }
            if (v1) {
                float a  = e1 * corr;
                float um = tau * u_var * r1;
                Wk[1] = Wkl1 + um * a;
                size_t idx = (size_t)(l * ZDIM + k) * PDIM + p1;
                out_mw[idx] = um;
                out_al[idx] = a;
            }

            pw0 = nm0 * na0;
            pw1 = nm1 * na1;
        }
        W[k][0] = Wk[0];
        W[k][1] = Wk[1];
    }
}

// ---------------------------------------------------------------------------
extern "C" void kernel_launch(void* const* d_in, const int* in_sizes, int n_in,
                              void* d_out, int out_size)
{
    (void)in_sizes; (void)n_in; (void)out_size;
    const float* data   = (const float*)d_in[0];
    const float* mean_z = (const float*)d_in[1];
    const float* var_z  = (const float*)d_in[2];
    const float* mean_w = (const float*)d_in[3];
    // d_in[4] = var_w (unused: vw output fully overwritten)
    const float* alpha  = (const float*)d_in[5];
    const float* tau_0  = (const float*)d_in[6];
    const float* pi     = (const float*)d_in[7];
    const float* tau    = (const float*)d_in[8];
    float* out = (float*)d_out;

    k1_ztr<<<K1_MAIN + 1, K1_THREADS>>>(data, mean_z, var_z, tau_0, tau,
                                        out + OUT_VW_OFF);
    k1b_reduce<<<K1B_BLOCKS, K1_THREADS>>>(mean_w, alpha);
    k2_loop<<<K2_BLOCKS, K2_THREADS>>>(mean_w, alpha, pi, tau_0, tau, out);
}